// round 16
// baseline (speedup 1.0000x reference)
#include <cuda_runtime.h>
#include <stdint.h>

#define BATCH 64
#define HH 1024
#define WW 1024
#define HWSZ (HH*WW)
#define NBINS 4096
#define CAP 4096
#define KMAX 256
#define NMS_R 0.05f
#define THRESH 3.6f
#define NBLK 1184                // 148 SMs x 8 resident CTAs: one-wave persistent grid
#define TOT4 (BATCH * HWSZ / 4)  // total float4 count

__device__ int g_count[BATCH];                       // zero-init; self-reset each run
__device__ unsigned long long g_cand[BATCH * CAP];

__device__ __forceinline__ unsigned int fkey(float x) {
    unsigned int u = __float_as_uint(x);
    return (u & 0x80000000u) ? ~u : (u | 0x80000000u);
}

__device__ __forceinline__ void emit_bin(float x, long long e, int b, unsigned int t12) {
    unsigned int kx = fkey(x);
    if ((kx >> 20) >= t12) {
        int s = atomicAdd(&g_count[b], 1);
        if (s < CAP) {
            unsigned int pos = (unsigned int)(e & (HWSZ - 1));
            g_cand[b * CAP + s] = ((unsigned long long)kx << 32) | (unsigned int)(~pos);
        }
    }
}

__device__ __forceinline__ void emit_hit(float x, unsigned int pos, int b) {
    unsigned int kx = __float_as_uint(x) | 0x80000000u;   // fkey for positive floats
    int s = atomicAdd(&g_count[b], 1);
    if (s < CAP)
        g_cand[b * CAP + s] = ((unsigned long long)kx << 32) | (unsigned int)(~pos);
}

// persistent balanced streaming pass: 1184 blocks, grid-stride over float4s.
__global__ void __launch_bounds__(256) k_collect_static(const float* __restrict__ hm) {
    const float4* p = (const float4*)hm;
    const unsigned int stride = NBLK * 256;
    unsigned int i4 = blockIdx.x * 256 + threadIdx.x;
#pragma unroll 4
    for (; i4 < TOT4; i4 += stride) {
        float4 v = p[i4];
        int b = i4 >> 18;                        // (i4*4) >> 20
        unsigned int pos = (i4 * 4u) & (HWSZ - 1);
        if (v.x >= THRESH) emit_hit(v.x, pos + 0, b);
        if (v.y >= THRESH) emit_hit(v.y, pos + 1, b);
        if (v.z >= THRESH) emit_hit(v.z, pos + 2, b);
        if (v.w >= THRESH) emit_hit(v.w, pos + 3, b);
    }
}

// per-batch finalize: speculative candidate load + rank selection + parallel NMS
__global__ void __launch_bounds__(256) k_finalize(const float* __restrict__ hm,
                                                  const int* __restrict__ ncp,
                                                  float* __restrict__ out) {
    const int b = blockIdx.x;
    __shared__ union {
        unsigned long long skey[CAP];
        int hist[NBINS];
    } u;
    __shared__ float2 co[KMAX];
    __shared__ unsigned long long adj[64];
    __shared__ int order[64];
    __shared__ int sh_sel;
    __shared__ unsigned int sh_t12;

    // all header loads independent, issued at cycle 0:
    const unsigned long long* cand = &g_cand[b * CAP];
    unsigned long long mykey = cand[threadIdx.x];   // speculative (CAP-sized: in-bounds)
    int c = g_count[b];
    int nc = ncp ? *ncp : 16;
    int K = 4 * nc; if (K > KMAX) K = KMAX; if (K > HWSZ) K = HWSZ;

    // ---- exact fallback if static threshold missed ----
    if (c < K || c > CAP) {
        for (int i = threadIdx.x; i < NBINS; i += 256) u.hist[i] = 0;
        __syncthreads();
        const float4* p = (const float4*)(hm + (long long)b * HWSZ);
        for (int i = threadIdx.x; i < HWSZ / 4; i += 256) {
            float4 v = p[i];
            atomicAdd(&u.hist[fkey(v.x) >> 20], 1);
            atomicAdd(&u.hist[fkey(v.y) >> 20], 1);
            atomicAdd(&u.hist[fkey(v.z) >> 20], 1);
            atomicAdd(&u.hist[fkey(v.w) >> 20], 1);
        }
        __syncthreads();
        if (threadIdx.x == 0) {
            long long acc = 0; unsigned int t = 0;
            for (int i = NBINS - 1; i >= 0; i--) {
                acc += u.hist[i];
                if (acc >= K) { t = (unsigned int)i; break; }
            }
            sh_t12 = t;
            g_count[b] = 0;
        }
        __syncthreads();
        unsigned int t = sh_t12;
        for (int i = threadIdx.x; i < HWSZ / 4; i += 256) {
            float4 v = p[i];
            long long e = 4LL * i;
            emit_bin(v.x, e + 0, b, t);
            emit_bin(v.y, e + 1, b, t);
            emit_bin(v.z, e + 2, b, t);
            emit_bin(v.w, e + 3, b, t);
        }
        __syncthreads();
        c = g_count[b];
        if (c > CAP) c = CAP;
        mykey = cand[threadIdx.x];              // re-load after refill
        __syncthreads();                        // union hist -> skey reuse safety
    }
    int Keff = (K < c) ? K : c;

    // ---- rank selection ----
    if (c <= 256) {
        u.skey[threadIdx.x] = mykey;
        __syncthreads();
        if (threadIdx.x < (unsigned)c) {
            int rank = 0;
            for (int j = 0; j < c; j++) rank += (u.skey[j] > mykey) ? 1 : 0;
            if (rank < Keff) {
                unsigned int pos = ~(unsigned int)(mykey & 0xFFFFFFFFULL);
                co[rank] = make_float2((float)(pos & (WW - 1)) / (float)(WW - 1),
                                       (float)(pos >> 10) / (float)(HH - 1));
            }
        }
    } else {
        for (int i = threadIdx.x; i < c; i += 256) u.skey[i] = cand[i];
        __syncthreads();
        for (int i = threadIdx.x; i < c; i += 256) {
            unsigned long long mk = u.skey[i];
            int rank = 0;
#pragma unroll 8
            for (int j = 0; j < c; j++) rank += (u.skey[j] > mk) ? 1 : 0;
            if (rank < Keff) {
                unsigned int pos = ~(unsigned int)(mk & 0xFFFFFFFFULL);
                co[rank] = make_float2((float)(pos & (WW - 1)) / (float)(WW - 1),
                                       (float)(pos >> 10) / (float)(HH - 1));
            }
        }
    }
    __syncthreads();

    // ---- greedy NMS ----
    int keep = (nc > 64) ? 64 : nc;
    if (Keff <= 64) {
        if (threadIdx.x < (unsigned)Keff) {
            int i = threadIdx.x;
            float x = co[i].x, y = co[i].y;
            unsigned long long m = 0;
            for (int j = 0; j < i; j++) {
                float dx = x - co[j].x, dy = y - co[j].y;
                if (sqrtf(dx * dx + dy * dy) < NMS_R) m |= (1ULL << j);
            }
            adj[i] = m;
        }
        __syncthreads();
        if (threadIdx.x == 0) {
            unsigned long long selmask = 0;
            int sel = 0;
#pragma unroll
            for (int i = 0; i < 64; i++) {
                bool ok = (i < Keff) && (sel < keep) && ((adj[i] & selmask) == 0);
                if (ok) {
                    selmask |= (1ULL << i);
                    order[sel] = i;
                    sel++;
                }
            }
            sh_sel = sel;
            g_count[b] = 0;                  // self-reset for next replay
        }
        __syncthreads();
        int sel = sh_sel;
        if (threadIdx.x < (unsigned)(2 * nc) && nc <= 128) {
            int s = threadIdx.x >> 1;
            int xy = threadIdx.x & 1;
            float val = 0.0f;
            if (s < sel) {
                float2 cc = co[order[s]];
                val = xy ? cc.y : cc.x;
            }
            out[((long long)b * nc + s) * 2 + xy] = val;
        } else if (threadIdx.x == 0 && nc > 128) {
            for (int s = 0; s < nc; s++) {
                float ox = 0.0f, oy = 0.0f;
                if (s < sel) { ox = co[order[s]].x; oy = co[order[s]].y; }
                out[((long long)b * nc + s) * 2 + 0] = ox;
                out[((long long)b * nc + s) * 2 + 1] = oy;
            }
        }
    } else {
        if (threadIdx.x == 0) {
            float sx[64], sy[64];
            int sel = 0;
            for (int i = 0; i < Keff && sel < keep; i++) {
                float x = co[i].x, y = co[i].y;
                bool close = false;
                for (int j = 0; j < sel; j++) {
                    float dx = x - sx[j], dy = y - sy[j];
                    if (sqrtf(dx * dx + dy * dy) < NMS_R) { close = true; break; }
                }
                if (!close) { sx[sel] = x; sy[sel] = y; sel++; }
            }
            for (int s = 0; s < nc; s++) {
                out[((long long)b * nc + s) * 2 + 0] = (s < sel) ? sx[s] : 0.0f;
                out[((long long)b * nc + s) * 2 + 1] = (s < sel) ? sy[s] : 0.0f;
            }
            g_count[b] = 0;
        }
    }
}

extern "C" void kernel_launch(void* const* d_in, const int* in_sizes, int n_in,
                              void* d_out, int out_size) {
    const float* hm = (const float*)d_in[0];
    const int* ncp = (n_in >= 2) ? (const int*)d_in[1] : nullptr;
    float* out = (float*)d_out;

    k_collect_static<<<NBLK, 256>>>(hm);
    k_finalize<<<BATCH, 256>>>(hm, ncp, out);
    (void)in_sizes; (void)out_size;
}

// round 17
// speedup vs baseline: 1.1109x; 1.1109x over previous
#include <cuda_runtime.h>
#include <stdint.h>

#define BATCH 64
#define HH 1024
#define WW 1024
#define HWSZ (HH*WW)
#define NBINS 4096
#define CAP 4096
#define KMAX 256
#define NMS_R 0.05f
#define THRESH 3.7f

__device__ int g_count[BATCH];                       // zero-init; self-reset each run
__device__ unsigned long long g_cand[BATCH * CAP];

__device__ __forceinline__ unsigned int fkey(float x) {
    unsigned int u = __float_as_uint(x);
    return (u & 0x80000000u) ? ~u : (u | 0x80000000u);
}

__device__ __forceinline__ void emit_bin(float x, long long e, int b, unsigned int t12) {
    unsigned int kx = fkey(x);
    if ((kx >> 20) >= t12) {
        int s = atomicAdd(&g_count[b], 1);
        if (s < CAP) {
            unsigned int pos = (unsigned int)(e & (HWSZ - 1));
            g_cand[b * CAP + s] = ((unsigned long long)kx << 32) | (unsigned int)(~pos);
        }
    }
}

__device__ __forceinline__ void emit_hit(float x, unsigned int pos, int b) {
    unsigned int kx = __float_as_uint(x) | 0x80000000u;   // fkey for positive floats
    int s = atomicAdd(&g_count[b], 1);
    if (s < CAP)
        g_cand[b * CAP + s] = ((unsigned long long)kx << 32) | (unsigned int)(~pos);
}

// pure streaming pass: single FSETP per element. 4096 elems/block. (proven 6.5 TB/s)
__global__ void __launch_bounds__(256) k_collect_static(const float* __restrict__ hm) {
    const long long base = (long long)blockIdx.x * 4096;
    const int b = (int)(base >> 20);
    const unsigned int inb = (unsigned int)(base & (HWSZ - 1));
    const float4* p = (const float4*)(hm + base);
#pragma unroll
    for (int it = 0; it < 4; it++) {
        int i = threadIdx.x + it * 256;
        float4 v = p[i];
        unsigned int pos = inb + 4u * i;
        if (v.x >= THRESH) emit_hit(v.x, pos + 0, b);
        if (v.y >= THRESH) emit_hit(v.y, pos + 1, b);
        if (v.z >= THRESH) emit_hit(v.z, pos + 2, b);
        if (v.w >= THRESH) emit_hit(v.w, pos + 3, b);
    }
}

// per-batch finalize: speculative candidate load + rank selection + parallel NMS
__global__ void __launch_bounds__(256) k_finalize(const float* __restrict__ hm,
                                                  const int* __restrict__ ncp,
                                                  float* __restrict__ out) {
    const int b = blockIdx.x;
    __shared__ union {
        unsigned long long skey[CAP];
        int hist[NBINS];
    } u;
    __shared__ float2 co[KMAX];
    __shared__ unsigned long long adj[64];
    __shared__ int order[64];
    __shared__ int sh_sel;
    __shared__ unsigned int sh_t12;

    // all header loads independent, issued at cycle 0:
    const unsigned long long* cand = &g_cand[b * CAP];
    unsigned long long mykey = cand[threadIdx.x];   // speculative (CAP-sized: in-bounds)
    int c = g_count[b];
    int nc = ncp ? *ncp : 16;
    int K = 4 * nc; if (K > KMAX) K = KMAX; if (K > HWSZ) K = HWSZ;

    // ---- exact fallback if static threshold missed ----
    if (c < K || c > CAP) {
        for (int i = threadIdx.x; i < NBINS; i += 256) u.hist[i] = 0;
        __syncthreads();
        const float4* p = (const float4*)(hm + (long long)b * HWSZ);
        for (int i = threadIdx.x; i < HWSZ / 4; i += 256) {
            float4 v = p[i];
            atomicAdd(&u.hist[fkey(v.x) >> 20], 1);
            atomicAdd(&u.hist[fkey(v.y) >> 20], 1);
            atomicAdd(&u.hist[fkey(v.z) >> 20], 1);
            atomicAdd(&u.hist[fkey(v.w) >> 20], 1);
        }
        __syncthreads();
        if (threadIdx.x == 0) {
            long long acc = 0; unsigned int t = 0;
            for (int i = NBINS - 1; i >= 0; i--) {
                acc += u.hist[i];
                if (acc >= K) { t = (unsigned int)i; break; }
            }
            sh_t12 = t;
            g_count[b] = 0;
        }
        __syncthreads();
        unsigned int t = sh_t12;
        for (int i = threadIdx.x; i < HWSZ / 4; i += 256) {
            float4 v = p[i];
            long long e = 4LL * i;
            emit_bin(v.x, e + 0, b, t);
            emit_bin(v.y, e + 1, b, t);
            emit_bin(v.z, e + 2, b, t);
            emit_bin(v.w, e + 3, b, t);
        }
        __syncthreads();
        c = g_count[b];
        if (c > CAP) c = CAP;
        mykey = cand[threadIdx.x];              // re-load after refill
        __syncthreads();                        // union hist -> skey reuse safety
    }
    int Keff = (K < c) ? K : c;

    // ---- rank selection ----
    if (c <= 256) {
        u.skey[threadIdx.x] = mykey;
        __syncthreads();
        if (threadIdx.x < (unsigned)c) {
            int rank = 0;
            for (int j = 0; j < c; j++) rank += (u.skey[j] > mykey) ? 1 : 0;
            if (rank < Keff) {
                unsigned int pos = ~(unsigned int)(mykey & 0xFFFFFFFFULL);
                co[rank] = make_float2((float)(pos & (WW - 1)) / (float)(WW - 1),
                                       (float)(pos >> 10) / (float)(HH - 1));
            }
        }
    } else {
        for (int i = threadIdx.x; i < c; i += 256) u.skey[i] = cand[i];
        __syncthreads();
        for (int i = threadIdx.x; i < c; i += 256) {
            unsigned long long mk = u.skey[i];
            int rank = 0;
#pragma unroll 8
            for (int j = 0; j < c; j++) rank += (u.skey[j] > mk) ? 1 : 0;
            if (rank < Keff) {
                unsigned int pos = ~(unsigned int)(mk & 0xFFFFFFFFULL);
                co[rank] = make_float2((float)(pos & (WW - 1)) / (float)(WW - 1),
                                       (float)(pos >> 10) / (float)(HH - 1));
            }
        }
    }
    __syncthreads();

    // ---- greedy NMS ----
    int keep = (nc > 64) ? 64 : nc;
    if (Keff <= 64) {
        if (threadIdx.x < (unsigned)Keff) {
            int i = threadIdx.x;
            float x = co[i].x, y = co[i].y;
            unsigned long long m = 0;
            for (int j = 0; j < i; j++) {
                float dx = x - co[j].x, dy = y - co[j].y;
                if (sqrtf(dx * dx + dy * dy) < NMS_R) m |= (1ULL << j);
            }
            adj[i] = m;
        }
        __syncthreads();
        if (threadIdx.x == 0) {
            unsigned long long selmask = 0;
            int sel = 0;
#pragma unroll
            for (int i = 0; i < 64; i++) {
                bool ok = (i < Keff) && (sel < keep) && ((adj[i] & selmask) == 0);
                if (ok) {
                    selmask |= (1ULL << i);
                    order[sel] = i;
                    sel++;
                }
            }
            sh_sel = sel;
            g_count[b] = 0;                  // self-reset for next replay
        }
        __syncthreads();
        int sel = sh_sel;
        if (threadIdx.x < (unsigned)(2 * nc) && nc <= 128) {
            int s = threadIdx.x >> 1;
            int xy = threadIdx.x & 1;
            float val = 0.0f;
            if (s < sel) {
                float2 cc = co[order[s]];
                val = xy ? cc.y : cc.x;
            }
            out[((long long)b * nc + s) * 2 + xy] = val;
        } else if (threadIdx.x == 0 && nc > 128) {
            for (int s = 0; s < nc; s++) {
                float ox = 0.0f, oy = 0.0f;
                if (s < sel) { ox = co[order[s]].x; oy = co[order[s]].y; }
                out[((long long)b * nc + s) * 2 + 0] = ox;
                out[((long long)b * nc + s) * 2 + 1] = oy;
            }
        }
    } else {
        if (threadIdx.x == 0) {
            float sx[64], sy[64];
            int sel = 0;
            for (int i = 0; i < Keff && sel < keep; i++) {
                float x = co[i].x, y = co[i].y;
                bool close = false;
                for (int j = 0; j < sel; j++) {
                    float dx = x - sx[j], dy = y - sy[j];
                    if (sqrtf(dx * dx + dy * dy) < NMS_R) { close = true; break; }
                }
                if (!close) { sx[sel] = x; sy[sel] = y; sel++; }
            }
            for (int s = 0; s < nc; s++) {
                out[((long long)b * nc + s) * 2 + 0] = (s < sel) ? sx[s] : 0.0f;
                out[((long long)b * nc + s) * 2 + 1] = (s < sel) ? sy[s] : 0.0f;
            }
            g_count[b] = 0;
        }
    }
}

extern "C" void kernel_launch(void* const* d_in, const int* in_sizes, int n_in,
                              void* d_out, int out_size) {
    const float* hm = (const float*)d_in[0];
    const int* ncp = (n_in >= 2) ? (const int*)d_in[1] : nullptr;
    float* out = (float*)d_out;

    k_collect_static<<<(BATCH * (long long)HWSZ) / 4096, 256>>>(hm);
    k_finalize<<<BATCH, 256>>>(hm, ncp, out);
    (void)in_sizes; (void)out_size;
}